// round 8
// baseline (speedup 1.0000x reference)
#include <cuda_runtime.h>
#include <cuda_fp16.h>
#include <cstdint>

#define DEVINL __device__ __forceinline__

// ---------------- problem constants ----------------
#define HID      64
#define NIN      32
#define TT       128
#define NB       8192
#define MT       64            // batch rows per CTA
#define NGATE    256           // 4*HID
#define KPAD     104           // padded K row stride (halves); real K = 96
#define NTHREADS 512
#define NCTAS    (NB / MT)     // 128

// ---------------- SMEM layout (bytes) ----------------
#define OFF_WFC  0                         // 512 f32
#define OFF_BFC  2048                      // 8 f32
#define OFF_AHI  4096
#define ASZ      (MT * KPAD * 2)           // 13312
#define OFF_ALO  (OFF_AHI + ASZ)
#define OFF_BHI  (OFF_ALO + ASZ)           // 30720
#define BSZ      (NGATE * KPAD * 2)        // 53248
#define OFF_BLO  (OFF_BHI + BSZ)           // 83968
#define OFF_G    (OFF_BLO + BSZ)           // 137216 ; gates [64][260] f32
#define GSTRIDE  1040                      // 260 f32 per row (pad kills conflicts)
#define SMEM_TOTAL (OFF_G + MT * GSTRIDE)  // 203776

// ---------------- PTX wrappers (ALL baseline ISA — no 'a' features) ----------------
DEVINL uint32_t smem_u32(const void* p) {
    uint32_t a;
    asm("{ .reg .u64 t; cvta.to.shared.u64 t, %1; cvt.u32.u64 %0, t; }" : "=r"(a) : "l"(p));
    return a;
}
DEVINL void ldsm4(uint32_t* r, uint32_t a) {
    asm volatile("ldmatrix.sync.aligned.m8n8.x4.shared.b16 {%0,%1,%2,%3}, [%4];"
                 : "=r"(r[0]), "=r"(r[1]), "=r"(r[2]), "=r"(r[3]) : "r"(a));
}
DEVINL void ldsm2(uint32_t* r, uint32_t a) {
    asm volatile("ldmatrix.sync.aligned.m8n8.x2.shared.b16 {%0,%1}, [%2];"
                 : "=r"(r[0]), "=r"(r[1]) : "r"(a));
}
DEVINL void mma16816(float* d, const uint32_t* a, const uint32_t* b) {
    asm volatile("mma.sync.aligned.m16n8k16.row.col.f32.f16.f16.f32 "
                 "{%0,%1,%2,%3}, {%4,%5,%6,%7}, {%8,%9}, {%0,%1,%2,%3};"
                 : "+f"(d[0]), "+f"(d[1]), "+f"(d[2]), "+f"(d[3])
                 : "r"(a[0]), "r"(a[1]), "r"(a[2]), "r"(a[3]), "r"(b[0]), "r"(b[1]));
}

// ---------------- fast accurate activations (ex2 + rcp, ~1e-7 rel) ----------------
DEVINL float ex2a(float x) { float y; asm("ex2.approx.f32 %0, %1;" : "=f"(y) : "f"(x)); return y; }
DEVINL float rcpa(float x) { float y; asm("rcp.approx.f32 %0, %1;" : "=f"(y) : "f"(x)); return y; }
DEVINL float sigm(float x)  { return rcpa(1.0f + ex2a(-1.4426950408889634f * x)); }
DEVINL float tanha(float x) { return 1.0f - 2.0f * rcpa(1.0f + ex2a(2.8853900817779268f * x)); }

// ---------------- kernel ----------------
__global__ void __launch_bounds__(NTHREADS, 1)
lstm_hmma_kernel(const float* __restrict__ X,
                 const float* __restrict__ Wih, const float* __restrict__ Whh,
                 const float* __restrict__ bih, const float* __restrict__ bhh,
                 const float* __restrict__ Wfc, const float* __restrict__ bfc,
                 float* __restrict__ out)
{
    extern __shared__ char sm[];
    const uint32_t sb = smem_u32(sm);
    const int tid  = threadIdx.x;
    const int lane = tid & 31, w = tid >> 5;
    const int mg = w >> 3;          // 0..1  (M warp group: 32 rows)
    const int ng = w & 7;           // 0..7  (N warp group: 32 gate cols)
    const int row0 = blockIdx.x * MT;

    // ---- zero A tiles (hi+lo contiguous) : h0 = 0, pads = 0 ----
    for (int i = tid; i < (2 * ASZ) / 16; i += NTHREADS)
        ((uint4*)(sm + OFF_AHI))[i] = make_uint4(0u, 0u, 0u, 0u);

    // ---- fill W tiles [n][k], split fp16 hi/lo.  Column n is gate-interleaved:
    //      n = 4*unit + gate  ->  original row srow = gate*64 + unit.
    //      K: [0,32) = W_ih, [32,96) = W_hh.  (bias goes into D init, not K.) ----
    for (int idx = tid; idx < NGATE * 96; idx += NTHREADS) {
        int n = idx / 96, k = idx - n * 96;
        int srow = ((n & 3) << 6) + (n >> 2);
        float v = (k < NIN) ? Wih[srow * NIN + k] : Whh[srow * HID + (k - NIN)];
        __half hv = __float2half_rn(v);
        __half lv = __float2half_rn(v - __half2float(hv));
        int off = (n * KPAD + k) * 2;
        *(__half*)(sm + OFF_BHI + off) = hv;
        *(__half*)(sm + OFF_BLO + off) = lv;
    }
    ((float*)(sm + OFF_WFC))[tid] = Wfc[tid];          // exactly 512 elems
    if (tid < 8) ((float*)(sm + OFF_BFC))[tid] = bfc[tid];

    // ---- per-thread bias for D init (depends only on column) ----
    float biasr[8];
#pragma unroll
    for (int q = 0; q < 8; q++) {
        int col  = ng * 32 + (q >> 1) * 8 + 2 * (lane & 3) + (q & 1);
        int srow = ((col & 3) << 6) + (col >> 2);
        biasr[q] = bih[srow] + bhh[srow];
    }

    // ---- activation-role mapping: thread -> (row, unit set {sl+8j}) ----
    const int arow = tid >> 3;     // 0..63
    const int sl   = tid & 7;

    // ---- x_0 into A (hi/lo fp16) ----
    {
        float4 xv = *(const float4*)(X + ((size_t)(row0 + arow) * TT + 0) * NIN + sl * 4);
        __half2 h0 = __floats2half2_rn(xv.x, xv.y);
        __half2 h1 = __floats2half2_rn(xv.z, xv.w);
        __half2 l0 = __floats2half2_rn(xv.x - __low2float(h0), xv.y - __high2float(h0));
        __half2 l1 = __floats2half2_rn(xv.z - __low2float(h1), xv.w - __high2float(h1));
        int off = (arow * KPAD + sl * 4) * 2;
        *(__half2*)(sm + OFF_AHI + off)     = h0;
        *(__half2*)(sm + OFF_AHI + off + 4) = h1;
        *(__half2*)(sm + OFF_ALO + off)     = l0;
        *(__half2*)(sm + OFF_ALO + off + 4) = l1;
    }
    __syncthreads();

    // ---- ldmatrix per-lane address offsets ----
    const int amat = lane >> 3;  // x4: 4 matrices (row-halves x k-halves)
    const uint32_t alane = (uint32_t)(((((amat & 1) << 3) + (lane & 7)) * KPAD + ((amat >> 1) << 3)) * 2);
    const uint32_t blane = (uint32_t)(((lane & 7) * KPAD + (((lane >> 3) & 1) << 3)) * 2);
    const uint32_t aBaseHi = sb + OFF_AHI + (uint32_t)(mg * 32 * KPAD * 2) + alane;
    const uint32_t aBaseLo = sb + OFF_ALO + (uint32_t)(mg * 32 * KPAD * 2) + alane;
    const uint32_t bBaseHi = sb + OFF_BHI + (uint32_t)(ng * 32 * KPAD * 2) + blane;
    const uint32_t bBaseLo = sb + OFF_BLO + (uint32_t)(ng * 32 * KPAD * 2) + blane;

    float c[8];
#pragma unroll
    for (int j = 0; j < 8; j++) c[j] = 0.0f;

#pragma unroll 1
    for (int t = 0; t < TT; t++) {
        // prefetch x_{t+1} (used ~3000 cyc later)
        float4 xv = make_float4(0.f, 0.f, 0.f, 0.f);
        if (t < TT - 1)
            xv = *(const float4*)(X + ((size_t)(row0 + arow) * TT + (t + 1)) * NIN + sl * 4);

        // ---- GEMM: gates = [x_t | h_{t-1}] . W^T + bias ; 3-term split fp16 ----
        float d[32];
#pragma unroll
        for (int mh = 0; mh < 2; mh++)
#pragma unroll
            for (int nt = 0; nt < 4; nt++) {
                int b = (mh * 4 + nt) * 4;
                d[b + 0] = biasr[nt * 2 + 0]; d[b + 1] = biasr[nt * 2 + 1];
                d[b + 2] = biasr[nt * 2 + 0]; d[b + 3] = biasr[nt * 2 + 1];
            }
#pragma unroll 1
        for (int kc = 0; kc < 6; kc++) {
            uint32_t ah[2][4], al[2][4], bh[4][2], bl[4][2];
#pragma unroll
            for (int mh = 0; mh < 2; mh++) {
                uint32_t off = (uint32_t)(mh * 16 * KPAD * 2 + kc * 32);
                ldsm4(ah[mh], aBaseHi + off);
                ldsm4(al[mh], aBaseLo + off);
            }
#pragma unroll
            for (int nt = 0; nt < 4; nt++) {
                uint32_t off = (uint32_t)(nt * 8 * KPAD * 2 + kc * 32);
                ldsm2(bh[nt], bBaseHi + off);
                ldsm2(bl[nt], bBaseLo + off);
            }
#pragma unroll
            for (int mh = 0; mh < 2; mh++)
#pragma unroll
                for (int nt = 0; nt < 4; nt++) {
                    float* dp = d + (mh * 4 + nt) * 4;
                    mma16816(dp, ah[mh], bh[nt]);   // hi*hi
                    mma16816(dp, ah[mh], bl[nt]);   // hi*lo (W compensation)
                    mma16816(dp, al[mh], bh[nt]);   // lo*hi (x/h compensation)
                }
        }
        // ---- D frags -> gates SMEM ----
#pragma unroll
        for (int mh = 0; mh < 2; mh++)
#pragma unroll
            for (int nt = 0; nt < 4; nt++) {
                int b   = (mh * 4 + nt) * 4;
                int r   = mg * 32 + mh * 16 + (lane >> 2);
                int col = ng * 32 + nt * 8 + 2 * (lane & 3);
                *(float2*)(sm + OFF_G + r * GSTRIDE + col * 4)       = make_float2(d[b + 0], d[b + 1]);
                *(float2*)(sm + OFF_G + (r + 8) * GSTRIDE + col * 4) = make_float2(d[b + 2], d[b + 3]);
            }
        __syncthreads();

        // ---- activations: each thread owns (row arow, units sl+8j) ----
        float h[8];
#pragma unroll
        for (int j = 0; j < 8; j++) {
            int u = sl + 8 * j;
            float4 gt = *(const float4*)(sm + OFF_G + arow * GSTRIDE + u * 16);
            float iv = sigm(gt.x), fv = sigm(gt.y), gv = tanha(gt.z), ov = sigm(gt.w);
            c[j] = fv * c[j] + iv * gv;
            h[j] = ov * tanha(c[j]);
        }

        if (t < TT - 1) {
            // h_t -> A tile (hi/lo), k = 32 + u
#pragma unroll
            for (int j = 0; j < 8; j++) {
                int u = sl + 8 * j;
                __half hh = __float2half_rn(h[j]);
                __half hl = __float2half_rn(h[j] - __half2float(hh));
                int off = (arow * KPAD + 32 + u) * 2;
                *(__half*)(sm + OFF_AHI + off) = hh;
                *(__half*)(sm + OFF_ALO + off) = hl;
            }
            // x_{t+1} -> A tile
            __half2 h0 = __floats2half2_rn(xv.x, xv.y);
            __half2 h1 = __floats2half2_rn(xv.z, xv.w);
            __half2 l0 = __floats2half2_rn(xv.x - __low2float(h0), xv.y - __high2float(h0));
            __half2 l1 = __floats2half2_rn(xv.z - __low2float(h1), xv.w - __high2float(h1));
            int off = (arow * KPAD + sl * 4) * 2;
            *(__half2*)(sm + OFF_AHI + off)     = h0;
            *(__half2*)(sm + OFF_AHI + off + 4) = h1;
            *(__half2*)(sm + OFF_ALO + off)     = l0;
            *(__half2*)(sm + OFF_ALO + off + 4) = l1;
            __syncthreads();
        } else {
            // final step: stage h_T (f32) into gates buffer (after all gate reads)
            __syncthreads();
#pragma unroll
            for (int j = 0; j < 8; j++) {
                int u = sl + 8 * j;
                *(float*)(sm + OFF_G + arow * GSTRIDE + u * 4) = h[j];
            }
        }
    }

    // ---- FC head: out = h_T @ Wfc^T + bfc ----
    __syncthreads();
    if (tid < MT) {
        const float* bf = (const float*)(sm + OFF_BFC);
        const float* wf = (const float*)(sm + OFF_WFC);
        float acc[8];
#pragma unroll
        for (int o = 0; o < 8; o++) acc[o] = bf[o];
        for (int j = 0; j < HID; j++) {
            float hv = *(const float*)(sm + OFF_G + tid * GSTRIDE + j * 4);
#pragma unroll
            for (int o = 0; o < 8; o++) acc[o] += hv * wf[o * HID + j];
        }
#pragma unroll
        for (int o = 0; o < 8; o++) out[(size_t)(row0 + tid) * 8 + o] = acc[o];
    }
}

extern "C" void kernel_launch(void* const* d_in, const int* in_sizes, int n_in,
                              void* d_out, int out_size) {
    const float* X   = (const float*)d_in[0];
    const float* Wih = (const float*)d_in[1];
    const float* Whh = (const float*)d_in[2];
    const float* bih = (const float*)d_in[3];
    const float* bhh = (const float*)d_in[4];
    const float* Wfc = (const float*)d_in[5];
    const float* bfc = (const float*)d_in[6];
    float* out = (float*)d_out;
    cudaFuncSetAttribute(lstm_hmma_kernel, cudaFuncAttributeMaxDynamicSharedMemorySize, SMEM_TOTAL);
    lstm_hmma_kernel<<<NCTAS, NTHREADS, SMEM_TOTAL>>>(X, Wih, Whh, bih, bhh, Wfc, bfc, out);
}

// round 9
// speedup vs baseline: 1.3194x; 1.3194x over previous
#include <cuda_runtime.h>
#include <cuda_fp16.h>
#include <cstdint>

#define DEVINL __device__ __forceinline__

// ---------------- problem constants ----------------
#define HID      64
#define NIN      32
#define TT       128
#define NB       8192
#define MT       32            // batch rows per CTA
#define NGATE    256           // 4*HID
#define KPAD     104           // padded K row stride (halves); real K = 96
#define NTHREADS 256
#define NCTAS    (NB / MT)     // 256

// ---------------- SMEM layout (bytes) ----------------
#define OFF_WFC  0                         // 512 f32
#define OFF_BFC  2048                      // 8 f32
#define OFF_AHI  4096
#define ASZ      (MT * KPAD * 2)           // 6656
#define OFF_ALO  (OFF_AHI + ASZ)           // 10752
#define OFF_BHI  (OFF_ALO + ASZ)           // 17408
#define BSZ      (NGATE * KPAD * 2)        // 53248
#define OFF_G    (OFF_BHI + BSZ)           // 70656 ; gates [32][260] f32
#define GSTRIDE  1040                      // 260 f32 per row (pad kills conflicts)
#define SMEM_TOTAL (OFF_G + MT * GSTRIDE)  // 103936  -> 2 CTAs/SM = 207872 < 228KB

// ---------------- PTX wrappers (baseline ISA only) ----------------
DEVINL uint32_t smem_u32(const void* p) {
    uint32_t a;
    asm("{ .reg .u64 t; cvta.to.shared.u64 t, %1; cvt.u32.u64 %0, t; }" : "=r"(a) : "l"(p));
    return a;
}
DEVINL void ldsm4(uint32_t* r, uint32_t a) {
    asm volatile("ldmatrix.sync.aligned.m8n8.x4.shared.b16 {%0,%1,%2,%3}, [%4];"
                 : "=r"(r[0]), "=r"(r[1]), "=r"(r[2]), "=r"(r[3]) : "r"(a));
}
DEVINL void ldsm2(uint32_t* r, uint32_t a) {
    asm volatile("ldmatrix.sync.aligned.m8n8.x2.shared.b16 {%0,%1}, [%2];"
                 : "=r"(r[0]), "=r"(r[1]) : "r"(a));
}
DEVINL void mma16816(float* d, const uint32_t* a, const uint32_t* b) {
    asm volatile("mma.sync.aligned.m16n8k16.row.col.f32.f16.f16.f32 "
                 "{%0,%1,%2,%3}, {%4,%5,%6,%7}, {%8,%9}, {%0,%1,%2,%3};"
                 : "+f"(d[0]), "+f"(d[1]), "+f"(d[2]), "+f"(d[3])
                 : "r"(a[0]), "r"(a[1]), "r"(a[2]), "r"(a[3]), "r"(b[0]), "r"(b[1]));
}

// ---------------- fast accurate activations (ex2 + rcp, ~1e-7 rel) ----------------
DEVINL float ex2a(float x) { float y; asm("ex2.approx.f32 %0, %1;" : "=f"(y) : "f"(x)); return y; }
DEVINL float rcpa(float x) { float y; asm("rcp.approx.f32 %0, %1;" : "=f"(y) : "f"(x)); return y; }
DEVINL float sigm(float x)  { return rcpa(1.0f + ex2a(-1.4426950408889634f * x)); }
DEVINL float tanha(float x) { return 1.0f - 2.0f * rcpa(1.0f + ex2a(2.8853900817779268f * x)); }

// ---------------- kernel ----------------
__global__ void __launch_bounds__(NTHREADS, 2)
lstm_hmma_kernel(const float* __restrict__ X,
                 const float* __restrict__ Wih, const float* __restrict__ Whh,
                 const float* __restrict__ bih, const float* __restrict__ bhh,
                 const float* __restrict__ Wfc, const float* __restrict__ bfc,
                 float* __restrict__ out)
{
    extern __shared__ char sm[];
    const uint32_t sb = smem_u32(sm);
    const int tid  = threadIdx.x;
    const int lane = tid & 31, w = tid >> 5;
    const int ng = w;               // 0..7 : warp tile = m32 x n32 at gate cols [32w, 32w+32)
    const int row0 = blockIdx.x * MT;

    // ---- zero A tiles (hi+lo contiguous): h0 = 0, K-pad = 0 ----
    for (int i = tid; i < (2 * ASZ) / 16; i += NTHREADS)
        ((uint4*)(sm + OFF_AHI))[i] = make_uint4(0u, 0u, 0u, 0u);

    // ---- fill W tile [n][k] (fp16 hi only).  Column n gate-interleaved:
    //      n = 4*unit + gate -> original row srow = gate*64 + unit.
    //      K: [0,32) = W_ih, [32,96) = W_hh.  (bias goes into D init.) ----
    for (int idx = tid; idx < NGATE * 96; idx += NTHREADS) {
        int n = idx / 96, k = idx - n * 96;
        int srow = ((n & 3) << 6) + (n >> 2);
        float v = (k < NIN) ? Wih[srow * NIN + k] : Whh[srow * HID + (k - NIN)];
        *(__half*)(sm + OFF_BHI + (n * KPAD + k) * 2) = __float2half_rn(v);
    }
    for (int i = tid; i < 512; i += NTHREADS) ((float*)(sm + OFF_WFC))[i] = Wfc[i];
    if (tid < 8) ((float*)(sm + OFF_BFC))[tid] = bfc[tid];

    // ---- per-thread bias for D init (depends only on column) ----
    float biasr[8];
#pragma unroll
    for (int q = 0; q < 8; q++) {
        int col  = ng * 32 + (q >> 1) * 8 + 2 * (lane & 3) + (q & 1);
        int srow = ((col & 3) << 6) + (col >> 2);
        biasr[q] = bih[srow] + bhh[srow];
    }

    // ---- activation-role mapping: thread -> (row, unit set {sl+8j}) ----
    const int arow = tid >> 3;     // 0..31
    const int sl   = tid & 7;

    // ---- x_0 into A (hi/lo fp16) ----
    {
        float4 xv = *(const float4*)(X + ((size_t)(row0 + arow) * TT + 0) * NIN + sl * 4);
        __half2 h0 = __floats2half2_rn(xv.x, xv.y);
        __half2 h1 = __floats2half2_rn(xv.z, xv.w);
        __half2 l0 = __floats2half2_rn(xv.x - __low2float(h0), xv.y - __high2float(h0));
        __half2 l1 = __floats2half2_rn(xv.z - __low2float(h1), xv.w - __high2float(h1));
        int off = (arow * KPAD + sl * 4) * 2;
        *(__half2*)(sm + OFF_AHI + off)     = h0;
        *(__half2*)(sm + OFF_AHI + off + 4) = h1;
        *(__half2*)(sm + OFF_ALO + off)     = l0;
        *(__half2*)(sm + OFF_ALO + off + 4) = l1;
    }
    __syncthreads();

    // ---- ldmatrix per-lane address offsets ----
    const int amat = lane >> 3;  // x4: 4 matrices (row-halves x k-halves)
    const uint32_t alane = (uint32_t)(((((amat & 1) << 3) + (lane & 7)) * KPAD + ((amat >> 1) << 3)) * 2);
    const uint32_t blane = (uint32_t)(((lane & 7) * KPAD + (((lane >> 3) & 1) << 3)) * 2);
    const uint32_t aBaseHi = sb + OFF_AHI + alane;
    const uint32_t aBaseLo = sb + OFF_ALO + alane;
    const uint32_t bBaseHi = sb + OFF_BHI + (uint32_t)(ng * 32 * KPAD * 2) + blane;

    float c[8];
#pragma unroll
    for (int j = 0; j < 8; j++) c[j] = 0.0f;

#pragma unroll 1
    for (int t = 0; t < TT; t++) {
        // prefetch x_{t+1} (consumed after the GEMM)
        float4 xv = make_float4(0.f, 0.f, 0.f, 0.f);
        if (t < TT - 1)
            xv = *(const float4*)(X + ((size_t)(row0 + arow) * TT + (t + 1)) * NIN + sl * 4);

        // ---- GEMM: gates = [x_t | h_{t-1}] . W^T + bias ; 2-term split fp16 ----
        float d[32];
#pragma unroll
        for (int mh = 0; mh < 2; mh++)
#pragma unroll
            for (int nt = 0; nt < 4; nt++) {
                int b = (mh * 4 + nt) * 4;
                d[b + 0] = biasr[nt * 2 + 0]; d[b + 1] = biasr[nt * 2 + 1];
                d[b + 2] = biasr[nt * 2 + 0]; d[b + 3] = biasr[nt * 2 + 1];
            }
#pragma unroll 1
        for (int kc = 0; kc < 6; kc++) {
            uint32_t ah[2][4], al[2][4], bh[4][2];
#pragma unroll
            for (int mh = 0; mh < 2; mh++) {
                uint32_t off = (uint32_t)(mh * 16 * KPAD * 2 + kc * 32);
                ldsm4(ah[mh], aBaseHi + off);
                ldsm4(al[mh], aBaseLo + off);
            }
#pragma unroll
            for (int nt = 0; nt < 4; nt++)
                ldsm2(bh[nt], bBaseHi + (uint32_t)(nt * 8 * KPAD * 2 + kc * 32));
#pragma unroll
            for (int mh = 0; mh < 2; mh++)
#pragma unroll
                for (int nt = 0; nt < 4; nt++) {
                    float* dp = d + (mh * 4 + nt) * 4;
                    mma16816(dp, ah[mh], bh[nt]);   // hi * W
                    mma16816(dp, al[mh], bh[nt]);   // state-residual compensation
                }
        }
        // ---- D frags -> gates SMEM ----
#pragma unroll
        for (int mh = 0; mh < 2; mh++)
#pragma unroll
            for (int nt = 0; nt < 4; nt++) {
                int b   = (mh * 4 + nt) * 4;
                int r   = mh * 16 + (lane >> 2);
                int col = ng * 32 + nt * 8 + 2 * (lane & 3);
                *(float2*)(sm + OFF_G + r * GSTRIDE + col * 4)       = make_float2(d[b + 0], d[b + 1]);
                *(float2*)(sm + OFF_G + (r + 8) * GSTRIDE + col * 4) = make_float2(d[b + 2], d[b + 3]);
            }
        __syncthreads();

        // ---- activations: thread owns (row arow, units sl+8j) ----
        float h[8];
#pragma unroll
        for (int j = 0; j < 8; j++) {
            int u = sl + 8 * j;
            float4 gt = *(const float4*)(sm + OFF_G + arow * GSTRIDE + u * 16);
            float iv = sigm(gt.x), fv = sigm(gt.y), gv = tanha(gt.z), ov = sigm(gt.w);
            c[j] = fv * c[j] + iv * gv;
            h[j] = ov * tanha(c[j]);
        }

        if (t < TT - 1) {
            // h_t -> A tile (hi/lo), k = 32 + u
#pragma unroll
            for (int j = 0; j < 8; j++) {
                int u = sl + 8 * j;
                __half hh = __float2half_rn(h[j]);
                __half hl = __float2half_rn(h[j] - __half2float(hh));
                int off = (arow * KPAD + 32 + u) * 2;
                *(__half*)(sm + OFF_AHI + off) = hh;
                *(__half*)(sm + OFF_ALO + off) = hl;
            }
            // x_{t+1} -> A tile
            __half2 h0 = __floats2half2_rn(xv.x, xv.y);
            __half2 h1 = __floats2half2_rn(xv.z, xv.w);
            __half2 l0 = __floats2half2_rn(xv.x - __low2float(h0), xv.y - __high2float(h0));
            __half2 l1 = __floats2half2_rn(xv.z - __low2float(h1), xv.w - __high2float(h1));
            int off = (arow * KPAD + sl * 4) * 2;
            *(__half2*)(sm + OFF_AHI + off)     = h0;
            *(__half2*)(sm + OFF_AHI + off + 4) = h1;
            *(__half2*)(sm + OFF_ALO + off)     = l0;
            *(__half2*)(sm + OFF_ALO + off + 4) = l1;
            __syncthreads();
        } else {
            // final step: stage h_T (f32) into gates buffer (after all gate reads)
            __syncthreads();
#pragma unroll
            for (int j = 0; j < 8; j++) {
                int u = sl + 8 * j;
                *(float*)(sm + OFF_G + arow * GSTRIDE + u * 4) = h[j];
            }
        }
    }

    // ---- FC head: out = h_T @ Wfc^T + bfc ----
    __syncthreads();
    if (tid < MT) {
        const float* bf = (const float*)(sm + OFF_BFC);
        const float* wf = (const float*)(sm + OFF_WFC);
        float acc[8];
#pragma unroll
        for (int o = 0; o < 8; o++) acc[o] = bf[o];
        for (int j = 0; j < HID; j++) {
            float hv = *(const float*)(sm + OFF_G + tid * GSTRIDE + j * 4);
#pragma unroll
            for (int o = 0; o < 8; o++) acc[o] += hv * wf[o * HID + j];
        }
#pragma unroll
        for (int o = 0; o < 8; o++) out[(size_t)(row0 + tid) * 8 + o] = acc[o];
    }
}

extern "C" void kernel_launch(void* const* d_in, const int* in_sizes, int n_in,
                              void* d_out, int out_size) {
    const float* X   = (const float*)d_in[0];
    const float* Wih = (const float*)d_in[1];
    const float* Whh = (const float*)d_in[2];
    const float* bih = (const float*)d_in[3];
    const float* bhh = (const float*)d_in[4];
    const float* Wfc = (const float*)d_in[5];
    const float* bfc = (const float*)d_in[6];
    float* out = (float*)d_out;
    cudaFuncSetAttribute(lstm_hmma_kernel, cudaFuncAttributeMaxDynamicSharedMemorySize, SMEM_TOTAL);
    lstm_hmma_kernel<<<NCTAS, NTHREADS, SMEM_TOTAL>>>(X, Wih, Whh, bih, bhh, Wfc, bfc, out);
}

// round 13
// speedup vs baseline: 1.3808x; 1.0465x over previous
#include <cuda_runtime.h>
#include <cuda_fp16.h>
#include <cstdint>

#define DEVINL __device__ __forceinline__

// ---------------- problem constants ----------------
#define HID      64
#define NIN      32
#define TT       128
#define NB       8192
#define MT       32            // batch rows per CTA
#define NGATE    256           // 4*HID
#define KPAD     104           // padded K row stride (halves); real K = 96
#define NTHREADS 256
#define NCTAS    (NB / MT)     // 256

// ---------------- SMEM layout (bytes) ----------------
#define OFF_WFC  0                          // 512 f32
#define OFF_BFC  2048                       // 8 f32
#define ASZ      (MT * KPAD * 2)            // 6656
#define OFF_A0HI 4096
#define OFF_A0LO (OFF_A0HI + ASZ)
#define OFF_A1HI (OFF_A0LO + ASZ)
#define OFF_A1LO (OFF_A1HI + ASZ)
#define BSZ      (NGATE * KPAD * 2)         // 53248
#define OFF_BHI  (OFF_A1LO + ASZ)           // 30720
#define OFF_HS   (OFF_BHI + BSZ)            // 83968 ; h_T staging [32][65] f32
#define HSTR     65
#define SMEM_TOTAL (OFF_HS + MT * HSTR * 4) // 92288  -> 2 CTAs/SM

// ---------------- PTX wrappers (baseline ISA only) ----------------
DEVINL uint32_t smem_u32(const void* p) {
    uint32_t a;
    asm("{ .reg .u64 t; cvta.to.shared.u64 t, %1; cvt.u32.u64 %0, t; }" : "=r"(a) : "l"(p));
    return a;
}
DEVINL void ldsm4(uint32_t* r, uint32_t a) {
    asm volatile("ldmatrix.sync.aligned.m8n8.x4.shared.b16 {%0,%1,%2,%3}, [%4];"
                 : "=r"(r[0]), "=r"(r[1]), "=r"(r[2]), "=r"(r[3]) : "r"(a));
}
DEVINL void ldsm2(uint32_t* r, uint32_t a) {
    asm volatile("ldmatrix.sync.aligned.m8n8.x2.shared.b16 {%0,%1}, [%2];"
                 : "=r"(r[0]), "=r"(r[1]) : "r"(a));
}
DEVINL void mma16816(float* d, const uint32_t* a, const uint32_t* b) {
    asm volatile("mma.sync.aligned.m16n8k16.row.col.f32.f16.f16.f32 "
                 "{%0,%1,%2,%3}, {%4,%5,%6,%7}, {%8,%9}, {%0,%1,%2,%3};"
                 : "+f"(d[0]), "+f"(d[1]), "+f"(d[2]), "+f"(d[3])
                 : "r"(a[0]), "r"(a[1]), "r"(a[2]), "r"(a[3]), "r"(b[0]), "r"(b[1]));
}

// ---------------- fast accurate activations (ex2 + rcp, ~1e-7 rel) ----------------
DEVINL float ex2a(float x) { float y; asm("ex2.approx.f32 %0, %1;" : "=f"(y) : "f"(x)); return y; }
DEVINL float rcpa(float x) { float y; asm("rcp.approx.f32 %0, %1;" : "=f"(y) : "f"(x)); return y; }
DEVINL float sigm(float x)  { return rcpa(1.0f + ex2a(-1.4426950408889634f * x)); }
DEVINL float tanha(float x) { return 1.0f - 2.0f * rcpa(1.0f + ex2a(2.8853900817779268f * x)); }

// ---------------- kernel ----------------
__global__ void __launch_bounds__(NTHREADS, 2)
lstm_hmma_kernel(const float* __restrict__ X,
                 const float* __restrict__ Wih, const float* __restrict__ Whh,
                 const float* __restrict__ bih, const float* __restrict__ bhh,
                 const float* __restrict__ Wfc, const float* __restrict__ bfc,
                 float* __restrict__ out)
{
    extern __shared__ char sm[];
    const uint32_t sb = smem_u32(sm);
    const int tid  = threadIdx.x;
    const int lane = tid & 31, w = tid >> 5;
    const int ng = w;               // warp tile: m32 x n32 at gate cols [32w, 32w+32)
    const int row0 = blockIdx.x * MT;

    // ---- zero both A buffers (hi+lo): h0 = 0, K-pads = 0 ----
    for (int i = tid; i < (4 * ASZ) / 16; i += NTHREADS)
        ((uint4*)(sm + OFF_A0HI))[i] = make_uint4(0u, 0u, 0u, 0u);

    // ---- W tile [n][k] (fp16 hi).  n gate-interleaved: n = 4*unit + gate ->
    //      original row srow = gate*64 + unit. K: [0,32)=W_ih, [32,96)=W_hh. ----
    for (int idx = tid; idx < NGATE * 96; idx += NTHREADS) {
        int n = idx / 96, k = idx - n * 96;
        int srow = ((n & 3) << 6) + (n >> 2);
        float v = (k < NIN) ? Wih[srow * NIN + k] : Whh[srow * HID + (k - NIN)];
        *(__half*)(sm + OFF_BHI + (n * KPAD + k) * 2) = __float2half_rn(v);
    }
    for (int i = tid; i < 512; i += NTHREADS) ((float*)(sm + OFF_WFC))[i] = Wfc[i];
    if (tid < 8) ((float*)(sm + OFF_BFC))[tid] = bfc[tid];

    // ---- per-thread bias for D init (depends only on column) ----
    float biasr[8];
#pragma unroll
    for (int q = 0; q < 8; q++) {
        int col  = ng * 32 + (q >> 1) * 8 + 2 * (lane & 3) + (q & 1);
        int srow = ((col & 3) << 6) + (col >> 2);
        biasr[q] = bih[srow] + bhh[srow];
    }

    // ---- x-loader role: thread -> (row arow, quarter sl) ----
    const int arow = tid >> 3;     // 0..31
    const int sl   = tid & 7;

    // ---- x_0 into A0 (hi/lo fp16) ----
    {
        float4 xv = *(const float4*)(X + ((size_t)(row0 + arow) * TT + 0) * NIN + sl * 4);
        __half2 h0 = __floats2half2_rn(xv.x, xv.y);
        __half2 h1 = __floats2half2_rn(xv.z, xv.w);
        __half2 l0 = __floats2half2_rn(xv.x - __low2float(h0), xv.y - __high2float(h0));
        __half2 l1 = __floats2half2_rn(xv.z - __low2float(h1), xv.w - __high2float(h1));
        int off = (arow * KPAD + sl * 4) * 2;
        *(__half2*)(sm + OFF_A0HI + off)     = h0;
        *(__half2*)(sm + OFF_A0HI + off + 4) = h1;
        *(__half2*)(sm + OFF_A0LO + off)     = l0;
        *(__half2*)(sm + OFF_A0LO + off + 4) = l1;
    }
    __syncthreads();

    // ---- ldmatrix per-lane address offsets ----
    const int amat = lane >> 3;
    const uint32_t alane = (uint32_t)(((((amat & 1) << 3) + (lane & 7)) * KPAD + ((amat >> 1) << 3)) * 2);
    const uint32_t blane = (uint32_t)(((lane & 7) * KPAD + (((lane >> 3) & 1) << 3)) * 2);
    const uint32_t aHiB[2] = { sb + OFF_A0HI + alane, sb + OFF_A1HI + alane };
    const uint32_t aLoB[2] = { sb + OFF_A0LO + alane, sb + OFF_A1LO + alane };
    const uint32_t bBaseHi = sb + OFF_BHI + (uint32_t)(ng * 32 * KPAD * 2) + blane;

    // mapping of owned (row, unit) per (mh, nt):
    const int rbase = (lane >> 2) + ((lane & 1) << 3);   // + mh*16
    const int ubase = ng * 8 + ((lane >> 1) & 1);        // + nt*2

    float c[8];
#pragma unroll
    for (int j = 0; j < 8; j++) c[j] = 0.0f;

#pragma unroll 1
    for (int t = 0; t < TT; t++) {
        const int rb = t & 1;
        // prefetch x_{t+1}
        float4 xv = make_float4(0.f, 0.f, 0.f, 0.f);
        if (t < TT - 1)
            xv = *(const float4*)(X + ((size_t)(row0 + arow) * TT + (t + 1)) * NIN + sl * 4);

        // ---- GEMM: gates = [x_t | h_{t-1}] . W^T + bias ; 2-term split fp16 ----
        float d[32];
#pragma unroll
        for (int mh = 0; mh < 2; mh++)
#pragma unroll
            for (int nt = 0; nt < 4; nt++) {
                int b = (mh * 4 + nt) * 4;
                d[b + 0] = biasr[nt * 2 + 0]; d[b + 1] = biasr[nt * 2 + 1];
                d[b + 2] = biasr[nt * 2 + 0]; d[b + 3] = biasr[nt * 2 + 1];
            }
#pragma unroll 1
        for (int kc = 0; kc < 6; kc++) {
            uint32_t ah[2][4], al[2][4], bh[4][2];
#pragma unroll
            for (int mh = 0; mh < 2; mh++) {
                uint32_t off = (uint32_t)(mh * 16 * KPAD * 2 + kc * 32);
                ldsm4(ah[mh], aHiB[rb] + off);
                ldsm4(al[mh], aLoB[rb] + off);
            }
#pragma unroll
            for (int nt = 0; nt < 4; nt++)
                ldsm2(bh[nt], bBaseHi + (uint32_t)(nt * 8 * KPAD * 2 + kc * 32));
#pragma unroll
            for (int mh = 0; mh < 2; mh++)
#pragma unroll
                for (int nt = 0; nt < 4; nt++) {
                    float* dp = d + (mh * 4 + nt) * 4;
                    mma16816(dp, ah[mh], bh[nt]);   // hi * W
                    mma16816(dp, al[mh], bh[nt]);   // state-residual compensation
                }
        }

        // ---- in-register gate exchange (lane pair shares one (row,unit)) + activations ----
        float hval[8];
#pragma unroll
        for (int mh = 0; mh < 2; mh++)
#pragma unroll
            for (int nt = 0; nt < 4; nt++) {
                int b = (mh * 4 + nt) * 4;
                float s0 = (lane & 1) ? d[b + 0] : d[b + 2];
                float s1 = (lane & 1) ? d[b + 1] : d[b + 3];
                float r0 = __shfl_xor_sync(0xffffffffu, s0, 1);
                float r1 = __shfl_xor_sync(0xffffffffu, s1, 1);
                float g0, g1, g2, g3;
                if (lane & 1) { g0 = r0;       g1 = r1;       g2 = d[b + 2]; g3 = d[b + 3]; }
                else          { g0 = d[b + 0]; g1 = d[b + 1]; g2 = r0;       g3 = r1;       }
                int j = mh * 4 + nt;
                float iv = sigm(g0), fv = sigm(g1), gv = tanha(g2), ov = sigm(g3);
                c[j] = fv * c[j] + iv * gv;
                hval[j] = ov * tanha(c[j]);
            }

        if (t < TT - 1) {
            // ---- h_t -> A[(t+1)&1] (hi/lo), col k = 32 + unit ----
            char* wHi = sm + (rb ? OFF_A0HI : OFF_A1HI);
            char* wLo = sm + (rb ? OFF_A0LO : OFF_A1LO);
#pragma unroll
            for (int mh = 0; mh < 2; mh++)
#pragma unroll
                for (int nt = 0; nt < 4; nt++) {
                    int j = mh * 4 + nt;
                    int r = mh * 16 + rbase;
                    int u = ubase + nt * 2;
                    __half hh = __float2half_rn(hval[j]);
                    __half hl = __float2half_rn(hval[j] - __half2float(hh));
                    int off = (r * KPAD + 32 + u) * 2;
                    *(__half*)(wHi + off) = hh;
                    *(__half*)(wLo + off) = hl;
                }
            // ---- x_{t+1} -> A[(t+1)&1] ----
            __half2 h0 = __floats2half2_rn(xv.x, xv.y);
            __half2 h1 = __floats2half2_rn(xv.z, xv.w);
            __half2 l0 = __floats2half2_rn(xv.x - __low2float(h0), xv.y - __high2float(h0));
            __half2 l1 = __floats2half2_rn(xv.z - __low2float(h1), xv.w - __high2float(h1));
            int off = (arow * KPAD + sl * 4) * 2;
            *(__half2*)(wHi + off)     = h0;
            *(__half2*)(wHi + off + 4) = h1;
            *(__half2*)(wLo + off)     = l0;
            *(__half2*)(wLo + off + 4) = l1;
            __syncthreads();
        } else {
            // ---- final step: stage h_T (f32) for the FC head ----
            float* hsm = (float*)(sm + OFF_HS);
#pragma unroll
            for (int mh = 0; mh < 2; mh++)
#pragma unroll
                for (int nt = 0; nt < 4; nt++) {
                    int j = mh * 4 + nt;
                    hsm[(mh * 16 + rbase) * HSTR + ubase + nt * 2] = hval[j];
                }
            __syncthreads();
        }
    }

    // ---- FC head: out = h_T @ Wfc^T + bfc ----
    if (tid < MT) {
        const float* bf  = (const float*)(sm + OFF_BFC);
        const float* wf  = (const float*)(sm + OFF_WFC);
        const float* hsm = (const float*)(sm + OFF_HS);
        float acc[8];
#pragma unroll
        for (int o = 0; o < 8; o++) acc[o] = bf[o];
        for (int j = 0; j < HID; j++) {
            float hv = hsm[tid * HSTR + j];
#pragma unroll
            for (int o = 0; o < 8; o++) acc[o] += hv * wf[o * HID + j];
        }
#pragma unroll
        for (int o = 0; o < 8; o++) out[(size_t)(row0 + tid) * 8 + o] = acc[o];
    }
}

extern "C" void kernel_launch(void* const* d_in, const int* in_sizes, int n_in,
                              void* d_out, int out_size) {
    const float* X   = (const float*)d_in[0];
    const float* Wih = (const float*)d_in[1];
    const float* Whh = (const float*)d_in[2];
    const float* bih = (const float*)d_in[3];
    const float* bhh = (const float*)d_in[4];
    const float* Wfc = (const float*)d_in[5];
    const float* bfc = (const float*)d_in[6];
    float* out = (float*)d_out;
    cudaFuncSetAttribute(lstm_hmma_kernel, cudaFuncAttributeMaxDynamicSharedMemorySize, SMEM_TOTAL);
    lstm_hmma_kernel<<<NCTAS, NTHREADS, SMEM_TOTAL>>>(X, Wih, Whh, bih, bhh, Wfc, bfc, out);
}

// round 15
// speedup vs baseline: 1.7521x; 1.2689x over previous
#include <cuda_runtime.h>
#include <cuda_fp16.h>
#include <cstdint>

#define DEVINL __device__ __forceinline__

// ---------------- problem constants ----------------
#define HID      64
#define NIN      32
#define TT       128
#define NB       8192
#define MT       32            // batch rows per CTA
#define NGATE    256           // 4*HID
#define KPAD     104           // padded K row stride (halves); real K = 96
#define NTHREADS 256
#define NCTAS    (NB / MT)     // 256

// ---------------- SMEM layout (bytes) ----------------
#define OFF_WFC  0                          // 512 f32
#define OFF_BFC  2048                       // 8 f32
#define ASZ      (MT * KPAD * 2)            // 6656
#define OFF_A0HI 4096
#define OFF_A0LO (OFF_A0HI + ASZ)
#define OFF_A1HI (OFF_A0LO + ASZ)
#define OFF_A1LO (OFF_A1HI + ASZ)
#define BSZ      (NGATE * KPAD * 2)         // 53248
#define OFF_BHI  (OFF_A1LO + ASZ)           // 30720
#define OFF_HS   (OFF_BHI + BSZ)            // 83968 ; h_T staging [32][65] f32
#define HSTR     65
#define SMEM_TOTAL (OFF_HS + MT * HSTR * 4) // 92288  -> 2 CTAs/SM

// ---------------- PTX wrappers (baseline ISA only) ----------------
DEVINL uint32_t smem_u32(const void* p) {
    uint32_t a;
    asm("{ .reg .u64 t; cvta.to.shared.u64 t, %1; cvt.u32.u64 %0, t; }" : "=r"(a) : "l"(p));
    return a;
}
DEVINL void ldsm4(uint32_t* r, uint32_t a) {
    asm volatile("ldmatrix.sync.aligned.m8n8.x4.shared.b16 {%0,%1,%2,%3}, [%4];"
                 : "=r"(r[0]), "=r"(r[1]), "=r"(r[2]), "=r"(r[3]) : "r"(a));
}
DEVINL void ldsm2(uint32_t* r, uint32_t a) {
    asm volatile("ldmatrix.sync.aligned.m8n8.x2.shared.b16 {%0,%1}, [%2];"
                 : "=r"(r[0]), "=r"(r[1]) : "r"(a));
}
DEVINL void mma16816(float* d, const uint32_t* a, const uint32_t* b) {
    asm volatile("mma.sync.aligned.m16n8k16.row.col.f32.f16.f16.f32 "
                 "{%0,%1,%2,%3}, {%4,%5,%6,%7}, {%8,%9}, {%0,%1,%2,%3};"
                 : "+f"(d[0]), "+f"(d[1]), "+f"(d[2]), "+f"(d[3])
                 : "r"(a[0]), "r"(a[1]), "r"(a[2]), "r"(a[3]), "r"(b[0]), "r"(b[1]));
}

// ---------------- fast activations via tanh.approx (1 MUFU each) ----------------
DEVINL float tanha(float x) { float y; asm("tanh.approx.f32 %0, %1;" : "=f"(y) : "f"(x)); return y; }
DEVINL float sigm(float x)  { return fmaf(0.5f, tanha(0.5f * x), 0.5f); }

// ---------------- kernel ----------------
__global__ void __launch_bounds__(NTHREADS, 2)
lstm_hmma_kernel(const float* __restrict__ X,
                 const float* __restrict__ Wih, const float* __restrict__ Whh,
                 const float* __restrict__ bih, const float* __restrict__ bhh,
                 const float* __restrict__ Wfc, const float* __restrict__ bfc,
                 float* __restrict__ out)
{
    extern __shared__ char sm[];
    const uint32_t sb = smem_u32(sm);
    const int tid  = threadIdx.x;
    const int lane = tid & 31, w = tid >> 5;
    const int ng = w;               // warp tile: m32 x n32 at gate cols [32w, 32w+32)
    const int row0 = blockIdx.x * MT;

    // ---- zero both A buffers (hi+lo): h0 = 0, K-pads = 0 ----
    for (int i = tid; i < (4 * ASZ) / 16; i += NTHREADS)
        ((uint4*)(sm + OFF_A0HI))[i] = make_uint4(0u, 0u, 0u, 0u);

    // ---- W tile [n][k] (fp16 hi).  n gate-interleaved: n = 4*unit + gate ->
    //      original row srow = gate*64 + unit. K: [0,32)=W_ih, [32,96)=W_hh. ----
    for (int idx = tid; idx < NGATE * 96; idx += NTHREADS) {
        int n = idx / 96, k = idx - n * 96;
        int srow = ((n & 3) << 6) + (n >> 2);
        float v = (k < NIN) ? Wih[srow * NIN + k] : Whh[srow * HID + (k - NIN)];
        *(__half*)(sm + OFF_BHI + (n * KPAD + k) * 2) = __float2half_rn(v);
    }
    for (int i = tid; i < 512; i += NTHREADS) ((float*)(sm + OFF_WFC))[i] = Wfc[i];
    if (tid < 8) ((float*)(sm + OFF_BFC))[tid] = bfc[tid];

    // ---- per-thread bias for D init (depends only on column) ----
    float biasr[8];
#pragma unroll
    for (int q = 0; q < 8; q++) {
        int col  = ng * 32 + (q >> 1) * 8 + 2 * (lane & 3) + (q & 1);
        int srow = ((col & 3) << 6) + (col >> 2);
        biasr[q] = bih[srow] + bhh[srow];
    }

    // ---- x-loader role: thread -> (row arow, quarter sl) ----
    const int arow = tid >> 3;     // 0..31
    const int sl   = tid & 7;

    // ---- x_0 into A0 (hi/lo fp16) ----
    {
        float4 xv = *(const float4*)(X + ((size_t)(row0 + arow) * TT + 0) * NIN + sl * 4);
        __half2 h0 = __floats2half2_rn(xv.x, xv.y);
        __half2 h1 = __floats2half2_rn(xv.z, xv.w);
        __half2 l0 = __floats2half2_rn(xv.x - __low2float(h0), xv.y - __high2float(h0));
        __half2 l1 = __floats2half2_rn(xv.z - __low2float(h1), xv.w - __high2float(h1));
        int off = (arow * KPAD + sl * 4) * 2;
        *(__half2*)(sm + OFF_A0HI + off)     = h0;
        *(__half2*)(sm + OFF_A0HI + off + 4) = h1;
        *(__half2*)(sm + OFF_A0LO + off)     = l0;
        *(__half2*)(sm + OFF_A0LO + off + 4) = l1;
    }
    __syncthreads();

    // ---- ldmatrix per-lane address offsets ----
    const int amat = lane >> 3;
    const uint32_t alane = (uint32_t)(((((amat & 1) << 3) + (lane & 7)) * KPAD + ((amat >> 1) << 3)) * 2);
    const uint32_t blane = (uint32_t)(((lane & 7) * KPAD + (((lane >> 3) & 1) << 3)) * 2);
    const uint32_t aHiB[2] = { sb + OFF_A0HI + alane, sb + OFF_A1HI + alane };
    const uint32_t aLoB[2] = { sb + OFF_A0LO + alane, sb + OFF_A1LO + alane };
    const uint32_t bBaseHi = sb + OFF_BHI + (uint32_t)(ng * 32 * KPAD * 2) + blane;

    // mapping of owned (row, unit) per (mh, nt):
    const int rbase = (lane >> 2) + ((lane & 1) << 3);   // + mh*16
    const int ubase = ng * 8 + ((lane >> 1) & 1);        // + nt*2

    float c[8];
#pragma unroll
    for (int j = 0; j < 8; j++) c[j] = 0.0f;

#pragma unroll 1
    for (int t = 0; t < TT; t++) {
        const int rb = t & 1;
        // prefetch x_{t+1}
        float4 xv = make_float4(0.f, 0.f, 0.f, 0.f);
        if (t < TT - 1)
            xv = *(const float4*)(X + ((size_t)(row0 + arow) * TT + (t + 1)) * NIN + sl * 4);

        // ---- GEMM: gates = [x_t | h_{t-1}] . W^T + bias ; 2-term split fp16 ----
        float d[32];
#pragma unroll
        for (int mh = 0; mh < 2; mh++)
#pragma unroll
            for (int nt = 0; nt < 4; nt++) {
                int b = (mh * 4 + nt) * 4;
                d[b + 0] = biasr[nt * 2 + 0]; d[b + 1] = biasr[nt * 2 + 1];
                d[b + 2] = biasr[nt * 2 + 0]; d[b + 3] = biasr[nt * 2 + 1];
            }
#pragma unroll 1
        for (int kc = 0; kc < 6; kc++) {
            uint32_t ah[2][4], al[2][4], bh[4][2];
#pragma unroll
            for (int mh = 0; mh < 2; mh++) {
                uint32_t off = (uint32_t)(mh * 16 * KPAD * 2 + kc * 32);
                ldsm4(ah[mh], aHiB[rb] + off);
                ldsm4(al[mh], aLoB[rb] + off);
            }
#pragma unroll
            for (int nt = 0; nt < 4; nt++)
                ldsm2(bh[nt], bBaseHi + (uint32_t)(nt * 8 * KPAD * 2 + kc * 32));
#pragma unroll
            for (int mh = 0; mh < 2; mh++)
#pragma unroll
                for (int nt = 0; nt < 4; nt++) {
                    float* dp = d + (mh * 4 + nt) * 4;
                    mma16816(dp, ah[mh], bh[nt]);   // hi * W
                    mma16816(dp, al[mh], bh[nt]);   // state-residual compensation
                }
        }

        // ---- in-register gate exchange (lane pair shares one (row,unit)) + activations ----
        float hval[8];
#pragma unroll
        for (int mh = 0; mh < 2; mh++)
#pragma unroll
            for (int nt = 0; nt < 4; nt++) {
                int b = (mh * 4 + nt) * 4;
                float s0 = (lane & 1) ? d[b + 0] : d[b + 2];
                float s1 = (lane & 1) ? d[b + 1] : d[b + 3];
                float r0 = __shfl_xor_sync(0xffffffffu, s0, 1);
                float r1 = __shfl_xor_sync(0xffffffffu, s1, 1);
                float g0, g1, g2, g3;
                if (lane & 1) { g0 = r0;       g1 = r1;       g2 = d[b + 2]; g3 = d[b + 3]; }
                else          { g0 = d[b + 0]; g1 = d[b + 1]; g2 = r0;       g3 = r1;       }
                int j = mh * 4 + nt;
                float iv = sigm(g0), fv = sigm(g1), gv = tanha(g2), ov = sigm(g3);
                c[j] = fv * c[j] + iv * gv;
                hval[j] = ov * tanha(c[j]);
            }

        if (t < TT - 1) {
            // ---- h_t -> A[(t+1)&1] (hi/lo), col k = 32 + unit ----
            char* wHi = sm + (rb ? OFF_A0HI : OFF_A1HI);
            char* wLo = sm + (rb ? OFF_A0LO : OFF_A1LO);
#pragma unroll
            for (int mh = 0; mh < 2; mh++)
#pragma unroll
                for (int nt = 0; nt < 4; nt++) {
                    int j = mh * 4 + nt;
                    int r = mh * 16 + rbase;
                    int u = ubase + nt * 2;
                    __half hh = __float2half_rn(hval[j]);
                    __half hl = __float2half_rn(hval[j] - __half2float(hh));
                    int off = (r * KPAD + 32 + u) * 2;
                    *(__half*)(wHi + off) = hh;
                    *(__half*)(wLo + off) = hl;
                }
            // ---- x_{t+1} -> A[(t+1)&1] ----
            __half2 h0 = __floats2half2_rn(xv.x, xv.y);
            __half2 h1 = __floats2half2_rn(xv.z, xv.w);
            __half2 l0 = __floats2half2_rn(xv.x - __low2float(h0), xv.y - __high2float(h0));
            __half2 l1 = __floats2half2_rn(xv.z - __low2float(h1), xv.w - __high2float(h1));
            int off = (arow * KPAD + sl * 4) * 2;
            *(__half2*)(wHi + off)     = h0;
            *(__half2*)(wHi + off + 4) = h1;
            *(__half2*)(wLo + off)     = l0;
            *(__half2*)(wLo + off + 4) = l1;
            __syncthreads();
        } else {
            // ---- final step: stage h_T (f32) for the FC head ----
            float* hsm = (float*)(sm + OFF_HS);
#pragma unroll
            for (int mh = 0; mh < 2; mh++)
#pragma unroll
                for (int nt = 0; nt < 4; nt++) {
                    int j = mh * 4 + nt;
                    hsm[(mh * 16 + rbase) * HSTR + ubase + nt * 2] = hval[j];
                }
            __syncthreads();
        }
    }

    // ---- FC head: out = h_T @ Wfc^T + bfc ----
    if (tid < MT) {
        const float* bf  = (const float*)(sm + OFF_BFC);
        const float* wf  = (const float*)(sm + OFF_WFC);
        const float* hsm = (const float*)(sm + OFF_HS);
        float acc[8];
#pragma unroll
        for (int o = 0; o < 8; o++) acc[o] = bf[o];
        for (int j = 0; j < HID; j++) {
            float hv = hsm[tid * HSTR + j];
#pragma unroll
            for (int o = 0; o < 8; o++) acc[o] += hv * wf[o * HID + j];
        }
#pragma unroll
        for (int o = 0; o < 8; o++) out[(size_t)(row0 + tid) * 8 + o] = acc[o];
    }
}

extern "C" void kernel_launch(void* const* d_in, const int* in_sizes, int n_in,
                              void* d_out, int out_size) {
    const float* X   = (const float*)d_in[0];
    const float* Wih = (const float*)d_in[1];
    const float* Whh = (const float*)d_in[2];
    const float* bih = (const float*)d_in[3];
    const float* bhh = (const float*)d_in[4];
    const float* Wfc = (const float*)d_in[5];
    const float* bfc = (const float*)d_in[6];
    float* out = (float*)d_out;
    cudaFuncSetAttribute(lstm_hmma_kernel, cudaFuncAttributeMaxDynamicSharedMemorySize, SMEM_TOTAL);
    lstm_hmma_kernel<<<NCTAS, NTHREADS, SMEM_TOTAL>>>(X, Wih, Whh, bih, bhh, Wfc, bfc, out);
}

// round 17
// speedup vs baseline: 2.6338x; 1.5032x over previous
#include <cuda_runtime.h>
#include <cuda_fp16.h>
#include <cstdint>

#define DEVINL __device__ __forceinline__

// ---------------- problem constants ----------------
#define HID      64
#define NIN      32
#define TT       128
#define NB       8192
#define MT       32            // batch rows per CTA
#define NGATE    256           // 4*HID
#define KPAD     104           // padded K row stride (halves); real K = 96
#define NTHREADS 256
#define NCTAS    (NB / MT)     // 256

// ---------------- SMEM layout (bytes) ----------------
#define OFF_WFC  0                          // 512 f32
#define OFF_BFC  2048                       // 8 f32
#define ASZ      (MT * KPAD * 2)            // 6656
#define OFF_A0   4096
#define OFF_A1   (OFF_A0 + ASZ)
#define BSZ      (NGATE * KPAD * 2)         // 53248
#define OFF_BHI  (OFF_A1 + ASZ)             // 17408
#define OFF_HS   (OFF_BHI + BSZ)            // 70656 ; h_T staging [32][65] f32
#define HSTR     65
#define SMEM_TOTAL (OFF_HS + MT * HSTR * 4) // 78976  -> 2 CTAs/SM

// ---------------- PTX wrappers (baseline ISA only) ----------------
DEVINL uint32_t smem_u32(const void* p) {
    uint32_t a;
    asm("{ .reg .u64 t; cvta.to.shared.u64 t, %1; cvt.u32.u64 %0, t; }" : "=r"(a) : "l"(p));
    return a;
}
DEVINL void ldsm4(uint32_t* r, uint32_t a) {
    asm volatile("ldmatrix.sync.aligned.m8n8.x4.shared.b16 {%0,%1,%2,%3}, [%4];"
                 : "=r"(r[0]), "=r"(r[1]), "=r"(r[2]), "=r"(r[3]) : "r"(a));
}
DEVINL void ldsm2(uint32_t* r, uint32_t a) {
    asm volatile("ldmatrix.sync.aligned.m8n8.x2.shared.b16 {%0,%1}, [%2];"
                 : "=r"(r[0]), "=r"(r[1]) : "r"(a));
}
DEVINL void mma16816(float* d, const uint32_t* a, const uint32_t* b) {
    asm volatile("mma.sync.aligned.m16n8k16.row.col.f32.f16.f16.f32 "
                 "{%0,%1,%2,%3}, {%4,%5,%6,%7}, {%8,%9}, {%0,%1,%2,%3};"
                 : "+f"(d[0]), "+f"(d[1]), "+f"(d[2]), "+f"(d[3])
                 : "r"(a[0]), "r"(a[1]), "r"(a[2]), "r"(a[3]), "r"(b[0]), "r"(b[1]));
}

// ---------------- fast activations via tanh.approx (1 MUFU each) ----------------
DEVINL float tanha(float x) { float y; asm("tanh.approx.f32 %0, %1;" : "=f"(y) : "f"(x)); return y; }
DEVINL float sigm(float x)  { return fmaf(0.5f, tanha(0.5f * x), 0.5f); }

// ---------------- kernel ----------------
__global__ void __launch_bounds__(NTHREADS, 2)
lstm_hmma_kernel(const float* __restrict__ X,
                 const float* __restrict__ Wih, const float* __restrict__ Whh,
                 const float* __restrict__ bih, const float* __restrict__ bhh,
                 const float* __restrict__ Wfc, const float* __restrict__ bfc,
                 float* __restrict__ out)
{
    extern __shared__ char sm[];
    const uint32_t sb = smem_u32(sm);
    const int tid  = threadIdx.x;
    const int lane = tid & 31, w = tid >> 5;
    const int ng = w;               // warp tile: m32 x n32 at gate cols [32w, 32w+32)
    const int row0 = blockIdx.x * MT;

    // ---- zero both A buffers: h0 = 0, K-pads = 0 ----
    for (int i = tid; i < (2 * ASZ) / 16; i += NTHREADS)
        ((uint4*)(sm + OFF_A0))[i] = make_uint4(0u, 0u, 0u, 0u);

    // ---- W tile [n][k] (fp16).  n gate-interleaved: n = 4*unit + gate ->
    //      original row srow = gate*64 + unit. K: [0,32)=W_ih, [32,96)=W_hh. ----
    for (int idx = tid; idx < NGATE * 96; idx += NTHREADS) {
        int n = idx / 96, k = idx - n * 96;
        int srow = ((n & 3) << 6) + (n >> 2);
        float v = (k < NIN) ? Wih[srow * NIN + k] : Whh[srow * HID + (k - NIN)];
        *(__half*)(sm + OFF_BHI + (n * KPAD + k) * 2) = __float2half_rn(v);
    }
    for (int i = tid; i < 512; i += NTHREADS) ((float*)(sm + OFF_WFC))[i] = Wfc[i];
    if (tid < 8) ((float*)(sm + OFF_BFC))[tid] = bfc[tid];

    // ---- per-thread bias for D init (depends only on column) ----
    float biasr[8];
#pragma unroll
    for (int q = 0; q < 8; q++) {
        int col  = ng * 32 + (q >> 1) * 8 + 2 * (lane & 3) + (q & 1);
        int srow = ((col & 3) << 6) + (col >> 2);
        biasr[q] = bih[srow] + bhh[srow];
    }

    // ---- x-loader role: thread -> (row arow, quarter sl) ----
    const int arow = tid >> 3;     // 0..31
    const int sl   = tid & 7;

    // ---- x_0 into A0 (fp16) ----
    {
        float4 xv = *(const float4*)(X + ((size_t)(row0 + arow) * TT + 0) * NIN + sl * 4);
        int off = (arow * KPAD + sl * 4) * 2;
        *(__half2*)(sm + OFF_A0 + off)     = __floats2half2_rn(xv.x, xv.y);
        *(__half2*)(sm + OFF_A0 + off + 4) = __floats2half2_rn(xv.z, xv.w);
    }
    __syncthreads();

    // ---- ldmatrix per-lane address offsets ----
    const int amat = lane >> 3;
    const uint32_t alane = (uint32_t)(((((amat & 1) << 3) + (lane & 7)) * KPAD + ((amat >> 1) << 3)) * 2);
    const uint32_t blane = (uint32_t)(((lane & 7) * KPAD + (((lane >> 3) & 1) << 3)) * 2);
    const uint32_t aB[2] = { sb + OFF_A0 + alane, sb + OFF_A1 + alane };
    const uint32_t bBaseHi = sb + OFF_BHI + (uint32_t)(ng * 32 * KPAD * 2) + blane;

    // mapping of owned (row, unit) per (mh, nt):
    const int rbase = (lane >> 2) + ((lane & 1) << 3);   // + mh*16
    const int ubase = ng * 8 + ((lane >> 1) & 1);        // + nt*2

    float c[8];
#pragma unroll
    for (int j = 0; j < 8; j++) c[j] = 0.0f;

#pragma unroll 1
    for (int t = 0; t < TT; t++) {
        const int rb = t & 1;
        // prefetch x_{t+1}
        float4 xv = make_float4(0.f, 0.f, 0.f, 0.f);
        if (t < TT - 1)
            xv = *(const float4*)(X + ((size_t)(row0 + arow) * TT + (t + 1)) * NIN + sl * 4);

        // ---- GEMM: gates = [x_t | h_{t-1}] . W^T + bias ; plain fp16 ----
        float d[32];
#pragma unroll
        for (int mh = 0; mh < 2; mh++)
#pragma unroll
            for (int nt = 0; nt < 4; nt++) {
                int b = (mh * 4 + nt) * 4;
                d[b + 0] = biasr[nt * 2 + 0]; d[b + 1] = biasr[nt * 2 + 1];
                d[b + 2] = biasr[nt * 2 + 0]; d[b + 3] = biasr[nt * 2 + 1];
            }
#pragma unroll 1
        for (int kc = 0; kc < 6; kc++) {
            uint32_t ah[2][4], bh[4][2];
#pragma unroll
            for (int mh = 0; mh < 2; mh++)
                ldsm4(ah[mh], aB[rb] + (uint32_t)(mh * 16 * KPAD * 2 + kc * 32));
#pragma unroll
            for (int nt = 0; nt < 4; nt++)
                ldsm2(bh[nt], bBaseHi + (uint32_t)(nt * 8 * KPAD * 2 + kc * 32));
#pragma unroll
            for (int mh = 0; mh < 2; mh++)
#pragma unroll
                for (int nt = 0; nt < 4; nt++)
                    mma16816(d + (mh * 4 + nt) * 4, ah[mh], bh[nt]);
        }

        // ---- in-register gate exchange (lane pair shares one (row,unit)) + activations ----
        float hval[8];
#pragma unroll
        for (int mh = 0; mh < 2; mh++)
#pragma unroll
            for (int nt = 0; nt < 4; nt++) {
                int b = (mh * 4 + nt) * 4;
                float s0 = (lane & 1) ? d[b + 0] : d[b + 2];
                float s1 = (lane & 1) ? d[b + 1] : d[b + 3];
                float r0 = __shfl_xor_sync(0xffffffffu, s0, 1);
                float r1 = __shfl_xor_sync(0xffffffffu, s1, 1);
                float g0, g1, g2, g3;
                if (lane & 1) { g0 = r0;       g1 = r1;       g2 = d[b + 2]; g3 = d[b + 3]; }
                else          { g0 = d[b + 0]; g1 = d[b + 1]; g2 = r0;       g3 = r1;       }
                int j = mh * 4 + nt;
                float iv = sigm(g0), fv = sigm(g1), gv = tanha(g2), ov = sigm(g3);
                c[j] = fv * c[j] + iv * gv;
                hval[j] = ov * tanha(c[j]);
            }

        if (t < TT - 1) {
            // ---- h_t -> A[(t+1)&1] (fp16), col k = 32 + unit ----
            char* wA = sm + (rb ? OFF_A0 : OFF_A1);
#pragma unroll
            for (int mh = 0; mh < 2; mh++)
#pragma unroll
                for (int nt = 0; nt < 4; nt++) {
                    int j = mh * 4 + nt;
                    int r = mh * 16 + rbase;
                    int u = ubase + nt * 2;
                    *(__half*)(wA + (r * KPAD + 32 + u) * 2) = __float2half_rn(hval[j]);
                }
            // ---- x_{t+1} -> A[(t+1)&1] ----
            int off = (arow * KPAD + sl * 4) * 2;
            *(__half2*)(wA + off)     = __floats2half2_rn(xv.x, xv.y);
            *(__half2*)(wA + off + 4) = __floats2half2_rn(xv.z, xv.w);
            __syncthreads();
        } else {
            // ---- final step: stage h_T (f32) for the FC head ----
            float* hsm = (float*)(sm + OFF_HS);
#pragma unroll
            for (int mh = 0; mh < 2; mh++)
#pragma unroll
                for (int nt = 0; nt < 4; nt++) {
                    int j = mh * 4 + nt;
                    hsm[(mh * 16 + rbase) * HSTR + ubase + nt * 2] = hval[j];
                }
            __syncthreads();
        }
    }

    // ---- FC head: out = h_T @ Wfc^T + bfc ----
    if (tid < MT) {
        const float* bf  = (const float*)(sm + OFF_BFC);
        const float* wf  = (const float*)(sm + OFF_WFC);
        const float* hsm = (const float*)(sm + OFF_HS);
        float acc[8];
#pragma unroll
        for (int o = 0; o < 8; o++) acc[o] = bf[o];
        for (int j = 0; j < HID; j++) {
            float hv = hsm[tid * HSTR + j];
#pragma unroll
            for (int o = 0; o < 8; o++) acc[o] += hv * wf[o * HID + j];
        }
#pragma unroll
        for (int o = 0; o < 8; o++) out[(size_t)(row0 + tid) * 8 + o] = acc[o];
    }
}

extern "C" void kernel_launch(void* const* d_in, const int* in_sizes, int n_in,
                              void* d_out, int out_size) {
    const float* X   = (const float*)d_in[0];
    const float* Wih = (const float*)d_in[1];
    const float* Whh = (const float*)d_in[2];
    const float* bih = (const float*)d_in[3];
    const float* bhh = (const float*)d_in[4];
    const float* Wfc = (const float*)d_in[5];
    const float* bfc = (const float*)d_in[6];
    float* out = (float*)d_out;
    cudaFuncSetAttribute(lstm_hmma_kernel, cudaFuncAttributeMaxDynamicSharedMemorySize, SMEM_TOTAL);
    lstm_hmma_kernel<<<NCTAS, NTHREADS, SMEM_TOTAL>>>(X, Wih, Whh, bih, bhh, Wfc, bfc, out);
}